// round 9
// baseline (speedup 1.0000x reference)
#include <cuda_runtime.h>
#include <cuda_bf16.h>
#include <cstdint>
#include <cfloat>

// Enable tcgen05 only on arch-specific (sm_10xa) compilation passes; the plain
// compute_103 pass compiles a stub (runtime falls back to exact scan).
#if defined(__CUDA_ARCH__) && (defined(__CUDA_ARCH_FEAT_SM103_ALL) || defined(__CUDA_ARCH_FEAT_SM100_ALL) || defined(__CUDA_ARCH_FEAT_SM101_ALL))
#define HAS_TCGEN05 1
#else
#define HAS_TCGEN05 0
#endif

// ---------------- problem constants ----------------
constexpr int N_TOK = 16384;
constexpr int K_CB  = 8192;
constexpr int D_DIM = 256;

constexpr int BM = 128;                 // tokens per CTA (M tile)
constexpr int BN = 128;                 // codes per chunk (N tile)
constexpr int NCHUNK = K_CB / BN;       // 64
constexpr int CAP_H = 64;               // candidate slots per (token, half)
constexpr float MARGIN = 2.0f;          // collection margin (>> 2*max bf16 dist err)
constexpr float RESCORE_MARGIN = 1.0f;  // exact-rescore window (>= 2*max err)

// ---------------- device scratch ----------------
__device__ __align__(16) __nv_bfloat16 g_Xb[N_TOK * D_DIM];
__device__ __align__(16) __nv_bfloat16 g_Eb[K_CB * D_DIM];
__device__ float g_esq[K_CB];
__device__ int   g_cand_idx[N_TOK * 2 * CAP_H];
__device__ float g_cand_scr[N_TOK * 2 * CAP_H];
__device__ int   g_cand_cnt[N_TOK * 2];

// ---------------- PTX helpers ----------------
__device__ __forceinline__ uint32_t smem_u32(const void* p) {
    uint32_t a;
    asm("{ .reg .u64 t; cvta.to.shared.u64 t, %1; cvt.u32.u64 %0, t; }" : "=r"(a) : "l"(p));
    return a;
}

#if HAS_TCGEN05
__device__ __forceinline__ uint32_t elect_one() {
    uint32_t p;
    asm volatile("{ .reg .pred p; elect.sync _|p, 0xFFFFFFFF; selp.b32 %0, 1, 0, p; }" : "=r"(p));
    return p;
}
#define MBAR_INIT(a, n) asm volatile("mbarrier.init.shared.b64 [%0], %1;" :: "r"(a), "r"(n) : "memory")
#define MBAR_ARRIVE(a)  asm volatile("mbarrier.arrive.release.cta.shared::cta.b64 _, [%0];" :: "r"(a) : "memory")
#define MBAR_WAIT(a, ph) do {                                                         \
    uint32_t _m = (a); uint32_t _p = (ph); uint32_t _d;                               \
    asm volatile("{ .reg .pred p; mbarrier.try_wait.parity.acquire.cta.shared::cta.b64 p, [%1], %2; selp.b32 %0, 1, 0, p; }" \
        : "=r"(_d) : "r"(_m), "r"(_p) : "memory");                                    \
    if (!_d) {                                                                        \
        asm volatile("{ .reg .pred P1; WL_%=: mbarrier.try_wait.parity.acquire.cta.shared::cta.b64 P1, [%0], %1, 0x989680; @P1 bra.uni WD_%=; bra.uni WL_%=; WD_%=: }" \
            :: "r"(_m), "r"(_p) : "memory");                                          \
    }                                                                                 \
} while (0)

#define TC_ALLOC(sa, n)   asm volatile("tcgen05.alloc.cta_group::1.sync.aligned.shared::cta.b32 [%0], %1;" :: "r"(sa), "r"(n) : "memory")
#define TC_DEALLOC(t, n)  asm volatile("tcgen05.dealloc.cta_group::1.sync.aligned.b32 %0, %1;" :: "r"(t), "r"(n))
#define TC_RELINQ()       asm volatile("tcgen05.relinquish_alloc_permit.cta_group::1.sync.aligned;")
#define TC_COMMIT(mb)     asm volatile("tcgen05.commit.cta_group::1.mbarrier::arrive::one.shared::cluster.b64 [%0];" :: "r"(mb) : "memory")
#define TC_FENCE_BEFORE() asm volatile("tcgen05.fence::before_thread_sync;" ::: "memory")
#define TC_FENCE_AFTER()  asm volatile("tcgen05.fence::after_thread_sync;" ::: "memory")
#define TC_WAIT_LD()      asm volatile("tcgen05.wait::ld.sync.aligned;" ::: "memory")
#define FENCE_ASYNC()     asm volatile("fence.proxy.async.shared::cta;" ::: "memory")

#define TC_LD_X32(r, ta) \
    asm volatile( \
        "tcgen05.ld.sync.aligned.32x32b.x32.b32 " \
        "{%0, %1, %2, %3, %4, %5, %6, %7, " \
        " %8, %9, %10, %11, %12, %13, %14, %15, " \
        " %16, %17, %18, %19, %20, %21, %22, %23, " \
        " %24, %25, %26, %27, %28, %29, %30, %31}, [%32];" \
        : "=r"((r)[0]),  "=r"((r)[1]),  "=r"((r)[2]),  "=r"((r)[3]), \
          "=r"((r)[4]),  "=r"((r)[5]),  "=r"((r)[6]),  "=r"((r)[7]), \
          "=r"((r)[8]),  "=r"((r)[9]),  "=r"((r)[10]), "=r"((r)[11]), \
          "=r"((r)[12]), "=r"((r)[13]), "=r"((r)[14]), "=r"((r)[15]), \
          "=r"((r)[16]), "=r"((r)[17]), "=r"((r)[18]), "=r"((r)[19]), \
          "=r"((r)[20]), "=r"((r)[21]), "=r"((r)[22]), "=r"((r)[23]), \
          "=r"((r)[24]), "=r"((r)[25]), "=r"((r)[26]), "=r"((r)[27]), \
          "=r"((r)[28]), "=r"((r)[29]), "=r"((r)[30]), "=r"((r)[31]) \
        : "r"(ta))

// SS-mode bf16 MMA, cta_group::1
__device__ __forceinline__ void mma_f16_ss(uint32_t d, uint64_t a, uint64_t b,
                                           uint32_t idesc, bool acc) {
    uint32_t en = acc ? 1u : 0u;
    asm volatile(
        "{\n\t.reg .pred p;\n\tsetp.ne.u32 p, %4, 0;\n\t"
        "tcgen05.mma.cta_group::1.kind::f16 [%0], %1, %2, %3, {%5,%5,%5,%5}, p;\n\t}"
        :: "r"(d), "l"(a), "l"(b), "r"(idesc), "r"(en), "r"(0u) : "memory");
}
#endif // HAS_TCGEN05

// SW128 K-major SMEM descriptor base (layout=SW128, version=1, SBO=64, LBO=1)
constexpr uint64_t DESC_BASE =
    (uint64_t(2) << 61) | (uint64_t(1) << 46) | (uint64_t(64) << 32) | (uint64_t(1) << 16);
__device__ __forceinline__ uint64_t make_desc(uint32_t smem_addr) {
    return DESC_BASE | ((uint64_t)(smem_addr >> 4) & 0x3FFF);
}

// idesc: f32 accum, bf16 A/B, K-major both, M=128, N=128
constexpr uint32_t MMA_IDESC =
    (1u << 4) | (1u << 7) | (1u << 10) | ((BN / 8) << 17) | ((BM / 16) << 24);

// Blocked-atom SW128 layout for a 128-row x 512-byte (256 bf16) tile.
__device__ __forceinline__ uint32_t tile_off(int row, int bytecol) {
    uint32_t off = (uint32_t)((((bytecol >> 7) << 4) + (row >> 3)) << 10)
                 + (uint32_t)((row & 7) << 7) + (uint32_t)(bytecol & 127);
    return off ^ ((off >> 3) & 0x70);
}
__device__ __forceinline__ uint32_t kstep_units(int k) {
    return (uint32_t)((k >> 2) * 1024 + (k & 3) * 2);
}

// ---------------- SMEM layout (offsets from the 1024-aligned base) ----------------
constexpr int SM_TMEMP = 0;
constexpr int SM_FULL0 = 8,  SM_FULL1 = 16;
constexpr int SM_MMA   = 24;                    // 4 x 8B : 24,32,40,48
constexpr int SM_EPI   = 56;                    // 4 x 8B : 56,64,72,80
constexpr int SM_ESQ   = 128;                   // 4 slots x 512B = 2048
constexpr int SM_X     = 4096;
constexpr int TILE_BYTES = BM * D_DIM * 2;      // 65536
constexpr int SM_E0    = SM_X + TILE_BYTES;
constexpr int SM_E1    = SM_E0 + TILE_BYTES;
constexpr int SMEM_TOTAL = SM_E1 + TILE_BYTES + 1024;   // alignment slack

constexpr int NTHREADS = 384;   // 8 epi warps + 1 MMA + 3 loaders

// ---------------- prep kernels ----------------
__global__ void prep_x(const float* __restrict__ X) {
    int i = blockIdx.x * blockDim.x + threadIdx.x;          // one uint4 (8 bf16) each
    const float4* s = reinterpret_cast<const float4*>(X) + (size_t)i * 2;
    float4 a = s[0], b = s[1];
    __nv_bfloat162 h0 = __floats2bfloat162_rn(a.x, a.y);
    __nv_bfloat162 h1 = __floats2bfloat162_rn(a.z, a.w);
    __nv_bfloat162 h2 = __floats2bfloat162_rn(b.x, b.y);
    __nv_bfloat162 h3 = __floats2bfloat162_rn(b.z, b.w);
    uint4 o;
    o.x = *reinterpret_cast<uint32_t*>(&h0);
    o.y = *reinterpret_cast<uint32_t*>(&h1);
    o.z = *reinterpret_cast<uint32_t*>(&h2);
    o.w = *reinterpret_cast<uint32_t*>(&h3);
    reinterpret_cast<uint4*>(g_Xb)[i] = o;
}

__global__ void prep_e(const float* __restrict__ E) {
    int gw = (blockIdx.x * blockDim.x + threadIdx.x) >> 5;
    int lane = threadIdx.x & 31;
    if (gw >= K_CB) return;
    const float4* e = reinterpret_cast<const float4*>(E + (size_t)gw * D_DIM);
    float4 v0 = e[lane], v1 = e[lane + 32];
    float s = v0.x * v0.x + v0.y * v0.y + v0.z * v0.z + v0.w * v0.w
            + v1.x * v1.x + v1.y * v1.y + v1.z * v1.z + v1.w * v1.w;
    __nv_bfloat162 h0 = __floats2bfloat162_rn(v0.x, v0.y);
    __nv_bfloat162 h1 = __floats2bfloat162_rn(v0.z, v0.w);
    __nv_bfloat162 h2 = __floats2bfloat162_rn(v1.x, v1.y);
    __nv_bfloat162 h3 = __floats2bfloat162_rn(v1.z, v1.w);
    uint2 o0 = { *reinterpret_cast<uint32_t*>(&h0), *reinterpret_cast<uint32_t*>(&h1) };
    uint2 o1 = { *reinterpret_cast<uint32_t*>(&h2), *reinterpret_cast<uint32_t*>(&h3) };
    *reinterpret_cast<uint2*>(g_Eb + (size_t)gw * D_DIM + lane * 4) = o0;
    *reinterpret_cast<uint2*>(g_Eb + (size_t)gw * D_DIM + 128 + lane * 4) = o1;
    #pragma unroll
    for (int o = 16; o > 0; o >>= 1) s += __shfl_xor_sync(0xFFFFFFFFu, s, o);
    if (lane == 0) g_esq[gw] = s;
}

// ---------------- stage 1 ----------------
__global__ void __launch_bounds__(NTHREADS, 1)
vq_stage1() {
    const int tid = threadIdx.x;
    const int rowBase = blockIdx.x * BM;
#if HAS_TCGEN05
    extern __shared__ char smem_raw[];
    const uint32_t sb0 = smem_u32(smem_raw);
    const uint32_t sb = (sb0 + 1023u) & ~1023u;        // 1024-aligned base
    char* smem = smem_raw + (sb - sb0);
    const int wid = tid >> 5;
    const int lane = tid & 31;

    if (wid == 8) {
        TC_ALLOC(sb + SM_TMEMP, 512);                  // 4 x 128-col D buffers
        TC_RELINQ();
    }
    if (tid == 0) {
        MBAR_INIT(sb + SM_FULL0, 96);  MBAR_INIT(sb + SM_FULL1, 96);
        #pragma unroll
        for (int i = 0; i < 4; i++) {
            MBAR_INIT(sb + SM_MMA + i * 8, 1);
            MBAR_INIT(sb + SM_EPI + i * 8, 256);
        }
    }
    __syncthreads();
    uint32_t tmem;
    asm volatile("ld.shared.b32 %0, [%1];" : "=r"(tmem) : "r"(sb + SM_TMEMP));

    // Stage X tile (128 x 256 bf16) once; all threads.
    for (int i = tid; i < 4096; i += NTHREADS) {
        int row = i >> 5, c16 = i & 31;
        uint4 v = *reinterpret_cast<const uint4*>(g_Xb + (size_t)(rowBase + row) * D_DIM + c16 * 8);
        *reinterpret_cast<uint4*>(smem + SM_X + tile_off(row, c16 * 16)) = v;
    }
    FENCE_ASYNC();
    __syncthreads();

    if (wid < 8) {
        // ---- epilogue: warp -> rows (wid&3)*32, col half (wid>>2) ----
        const int half  = wid >> 2;
        const int token = rowBase + (wid & 3) * 32 + lane;
        float best = FLT_MAX;
        int cnt = 0;
        int*   mylist = g_cand_idx + ((size_t)token * 2 + half) * CAP_H;
        float* myscr  = g_cand_scr + ((size_t)token * 2 + half) * CAP_H;

        for (int c = 0; c < NCHUNK; c++) {
            const int s4 = c & 3;
            MBAR_WAIT(sb + SM_MMA + s4 * 8, (c >> 2) & 1);
            TC_FENCE_AFTER();

            uint32_t r[64];
            const uint32_t tbase = tmem + (uint32_t)(s4 * 128 + half * 64);
            TC_LD_X32(r, tbase);
            TC_LD_X32(r + 32, tbase + 32);

            const float4* esm = reinterpret_cast<const float4*>(
                smem + SM_ESQ + s4 * 512 + half * 256);
            TC_WAIT_LD();

            float* sc = reinterpret_cast<float*>(r);
            #pragma unroll
            for (int g = 0; g < 16; g++) {
                float4 e = esm[g];
                sc[g*4+0] = fmaf(-2.0f, __uint_as_float(r[g*4+0]), e.x);
                sc[g*4+1] = fmaf(-2.0f, __uint_as_float(r[g*4+1]), e.y);
                sc[g*4+2] = fmaf(-2.0f, __uint_as_float(r[g*4+2]), e.z);
                sc[g*4+3] = fmaf(-2.0f, __uint_as_float(r[g*4+3]), e.w);
            }
            TC_FENCE_BEFORE();
            MBAR_ARRIVE(sb + SM_EPI + s4 * 8);    // TMEM buffer + esq slot free

            // log-depth min tree (no 63-deep serial chain)
            float mm[32];
            #pragma unroll
            for (int j = 0; j < 32; j++) mm[j] = fminf(sc[j], sc[j + 32]);
            #pragma unroll
            for (int st = 16; st >= 1; st >>= 1)
                #pragma unroll
                for (int j = 0; j < 16; j++)
                    if (j < st) mm[j] = fminf(mm[j], mm[j + st]);

            if (mm[0] < best + MARGIN) {          // rare: collect candidates
                const int colBase = c * BN + half * 64;
                #pragma unroll 4
                for (int j = 0; j < 64; j++) {
                    float v = sc[j];
                    if (v < best + MARGIN) {
                        if (cnt < CAP_H) { mylist[cnt] = colBase + j; myscr[cnt] = v; }
                        cnt++;
                        if (v < best) best = v;
                    }
                }
            }
        }
        g_cand_cnt[(size_t)token * 2 + half] = cnt;
    } else if (wid == 8) {
        // ---- MMA warp ----
        const uint64_t a_base = make_desc(sb + SM_X);
        for (int c = 0; c < NCHUNK; c++) {
            const int s2 = c & 1, s4 = c & 3;
            MBAR_WAIT(sb + (s2 ? SM_FULL1 : SM_FULL0), (c >> 1) & 1);
            if (c >= 4) MBAR_WAIT(sb + SM_EPI + s4 * 8, ((c - 4) >> 2) & 1);
            TC_FENCE_AFTER();
            if (elect_one()) {
                const uint64_t b_base = make_desc(sb + (s2 ? SM_E1 : SM_E0));
                #pragma unroll
                for (int k = 0; k < 16; k++) {
                    uint32_t u = kstep_units(k);
                    mma_f16_ss(tmem + (uint32_t)(s4 * 128), a_base + u, b_base + u,
                               MMA_IDESC, k > 0);
                }
                TC_COMMIT(sb + SM_MMA + s4 * 8);
            }
        }
    } else {
        // ---- loader warps (9..11, 96 threads) ----
        const int lt = tid - 288;
        for (int c = 0; c < NCHUNK; c++) {
            const int s2 = c & 1, s4 = c & 3;
            // E buffer s2 freed when MMA(c-2) finished reading SMEM
            if (c >= 2) MBAR_WAIT(sb + SM_MMA + ((c - 2) & 3) * 8, ((c - 2) >> 2) & 1);
            // esq slot s4 freed when EPI(c-4) consumed it
            if (c >= 4) MBAR_WAIT(sb + SM_EPI + s4 * 8, ((c - 4) >> 2) & 1);
            const int eoff = s2 ? SM_E1 : SM_E0;
            const size_t gbase = (size_t)(c * BN) * D_DIM;
            #pragma unroll 4
            for (int i = lt; i < 4096; i += 96) {
                int row = i >> 5, c16 = i & 31;
                uint4 v = *reinterpret_cast<const uint4*>(g_Eb + gbase + (size_t)row * D_DIM + c16 * 8);
                *reinterpret_cast<uint4*>(smem + eoff + tile_off(row, c16 * 16)) = v;
            }
            if (lt < 32) {   // esq chunk: 128 floats
                float4 v = *reinterpret_cast<const float4*>(g_esq + c * BN + lt * 4);
                *reinterpret_cast<float4*>(smem + SM_ESQ + s4 * 512 + lt * 16) = v;
            }
            FENCE_ASYNC();
            MBAR_ARRIVE(sb + (s2 ? SM_FULL1 : SM_FULL0));
        }
    }

    __syncthreads();
    if (wid == 8) TC_DEALLOC(tmem, 512);
#else
    // Stub pass: force stage-2 exact full scan for correctness.
    if (tid < BM) {
        g_cand_cnt[(size_t)(rowBase + tid) * 2 + 0] = CAP_H + 1;
        g_cand_cnt[(size_t)(rowBase + tid) * 2 + 1] = CAP_H + 1;
    }
#endif
}

// ---------------- stage 2: window-filtered exact rescore + gather ----------------
__global__ void vq_stage2(const float* __restrict__ X, const float* __restrict__ E,
                          float* __restrict__ out, int write_idx) {
    const int warp = (blockIdx.x * blockDim.x + threadIdx.x) >> 5;
    const int lane = threadIdx.x & 31;
    if (warp >= N_TOK) return;

    auto score = [&](int k, float4 x0, float4 x1) -> float {
        const float4* er = reinterpret_cast<const float4*>(E + (size_t)k * D_DIM) + lane * 2;
        float4 e0 = er[0], e1 = er[1];
        float d = x0.x * e0.x;
        d = fmaf(x0.y, e0.y, d); d = fmaf(x0.z, e0.z, d); d = fmaf(x0.w, e0.w, d);
        d = fmaf(x1.x, e1.x, d); d = fmaf(x1.y, e1.y, d);
        d = fmaf(x1.z, e1.z, d); d = fmaf(x1.w, e1.w, d);
        #pragma unroll
        for (int o = 16; o > 0; o >>= 1) d += __shfl_xor_sync(0xFFFFFFFFu, d, o);
        return fmaf(-2.0f, d, __ldg(&g_esq[k]));
    };

    const int cnt0 = g_cand_cnt[(size_t)warp * 2 + 0];
    const int cnt1 = g_cand_cnt[(size_t)warp * 2 + 1];
    int bi = 0;

    if (cnt0 <= CAP_H && cnt1 <= CAP_H) {
        const int*   l0 = g_cand_idx + (size_t)warp * 2 * CAP_H;
        const int*   l1 = l0 + CAP_H;
        const float* s0 = g_cand_scr + (size_t)warp * 2 * CAP_H;
        const float* s1 = s0 + CAP_H;

        // pass 1: min approx score
        float m = FLT_MAX;
        for (int t = 0; t < cnt0; t++) m = fminf(m, s0[t]);
        for (int t = 0; t < cnt1; t++) m = fminf(m, s1[t]);
        const float thr = m + RESCORE_MARGIN;

        // pass 2: collect window (true argmin is provably inside)
        int widx[16];
        int nw = 0;
        for (int t = 0; t < cnt0; t++)
            if (s0[t] < thr) { if (nw < 16) widx[nw] = l0[t]; nw++; }
        for (int t = 0; t < cnt1; t++)
            if (s1[t] < thr) { if (nw < 16) widx[nw] = l1[t]; nw++; }

        if (nw == 1) {
            bi = widx[0];                 // certain winner, no dot products
        } else {
            const float4* xr = reinterpret_cast<const float4*>(X + (size_t)warp * D_DIM) + lane * 2;
            const float4 x0 = xr[0], x1 = xr[1];
            float best = FLT_MAX;
            bi = 0x7FFFFFFF;
            if (nw <= 16) {
                for (int t = 0; t < nw; t++) {
                    int k = widx[t];
                    float scv = score(k, x0, x1);
                    if (scv < best || (scv == best && k < bi)) { best = scv; bi = k; }
                }
            } else {  // window overflow: rescore every candidate (rare)
                for (int t = 0; t < cnt0; t++) {
                    int k = l0[t];
                    float scv = score(k, x0, x1);
                    if (scv < best || (scv == best && k < bi)) { best = scv; bi = k; }
                }
                for (int t = 0; t < cnt1; t++) {
                    int k = l1[t];
                    float scv = score(k, x0, x1);
                    if (scv < best || (scv == best && k < bi)) { best = scv; bi = k; }
                }
            }
        }
    } else {
        // overflow / stub fallback: exact scan of all codes
        const float4* xr = reinterpret_cast<const float4*>(X + (size_t)warp * D_DIM) + lane * 2;
        const float4 x0 = xr[0], x1 = xr[1];
        float best = FLT_MAX;
        for (int k = 0; k < K_CB; k++) {
            float scv = score(k, x0, x1);
            if (scv < best) { best = scv; bi = k; }
        }
    }

    const float4* er = reinterpret_cast<const float4*>(E + (size_t)bi * D_DIM) + lane * 2;
    float4* outr = reinterpret_cast<float4*>(out + (size_t)warp * D_DIM) + lane * 2;
    outr[0] = er[0];
    outr[1] = er[1];
    if (write_idx && lane == 0)
        out[(size_t)N_TOK * D_DIM + warp] = (float)bi;
}

// ---------------- launcher ----------------
extern "C" void kernel_launch(void* const* d_in, const int* in_sizes, int n_in,
                              void* d_out, int out_size) {
    const float* X = (const float*)d_in[0];   // inputs_flatten [N, D]
    const float* E = (const float*)d_in[1];   // embed [K, D]
    float* out = (float*)d_out;

    cudaFuncSetAttribute(vq_stage1, cudaFuncAttributeMaxDynamicSharedMemorySize, SMEM_TOTAL);

    prep_x<<<(N_TOK * D_DIM / 8) / 256, 256>>>(X);
    prep_e<<<(K_CB * 32) / 256, 256>>>(E);
    vq_stage1<<<N_TOK / BM, NTHREADS, SMEM_TOTAL>>>();

    int write_idx = (out_size >= N_TOK * D_DIM + N_TOK) ? 1 : 0;
    vq_stage2<<<(N_TOK / 8), 256>>>(X, E, out, write_idx);
}

// round 10
// speedup vs baseline: 1.5369x; 1.5369x over previous
#include <cuda_runtime.h>
#include <cuda_bf16.h>
#include <cstdint>
#include <cfloat>

// Enable tcgen05 only on arch-specific (sm_10xa) compilation passes; the plain
// compute_103 pass compiles a stub (runtime falls back to exact scan).
#if defined(__CUDA_ARCH__) && (defined(__CUDA_ARCH_FEAT_SM103_ALL) || defined(__CUDA_ARCH_FEAT_SM100_ALL) || defined(__CUDA_ARCH_FEAT_SM101_ALL))
#define HAS_TCGEN05 1
#else
#define HAS_TCGEN05 0
#endif

// ---------------- problem constants ----------------
constexpr int N_TOK = 16384;
constexpr int K_CB  = 8192;
constexpr int D_DIM = 256;

constexpr int BM = 128;                 // tokens per CTA (M tile)
constexpr int BN = 128;                 // codes per chunk (N tile)
constexpr int NCHUNK = K_CB / BN;       // 64
constexpr int CAP_H = 64;               // candidate slots per (token, half)
constexpr float MARGIN = 2.0f;          // collection margin (>> 2*max bf16 dist err)
constexpr float RESCORE_MARGIN = 1.0f;  // exact-rescore window (>= 2*max err)

// ---------------- device scratch ----------------
__device__ __align__(16) __nv_bfloat16 g_Xb[N_TOK * D_DIM];
__device__ __align__(16) __nv_bfloat16 g_Eb[K_CB * D_DIM];
__device__ float g_esq[K_CB];
__device__ int   g_cand_idx[N_TOK * 2 * CAP_H];
__device__ float g_cand_scr[N_TOK * 2 * CAP_H];
__device__ int   g_cand_cnt[N_TOK * 2];

// ---------------- PTX helpers ----------------
__device__ __forceinline__ uint32_t smem_u32(const void* p) {
    uint32_t a;
    asm("{ .reg .u64 t; cvta.to.shared.u64 t, %1; cvt.u32.u64 %0, t; }" : "=r"(a) : "l"(p));
    return a;
}

#if HAS_TCGEN05
__device__ __forceinline__ uint32_t elect_one() {
    uint32_t p;
    asm volatile("{ .reg .pred p; elect.sync _|p, 0xFFFFFFFF; selp.b32 %0, 1, 0, p; }" : "=r"(p));
    return p;
}
#define MBAR_INIT(a, n) asm volatile("mbarrier.init.shared.b64 [%0], %1;" :: "r"(a), "r"(n) : "memory")
#define MBAR_ARRIVE(a)  asm volatile("mbarrier.arrive.release.cta.shared::cta.b64 _, [%0];" :: "r"(a) : "memory")
#define MBAR_WAIT(a, ph) do {                                                         \
    uint32_t _m = (a); uint32_t _p = (ph); uint32_t _d;                               \
    asm volatile("{ .reg .pred p; mbarrier.try_wait.parity.acquire.cta.shared::cta.b64 p, [%1], %2; selp.b32 %0, 1, 0, p; }" \
        : "=r"(_d) : "r"(_m), "r"(_p) : "memory");                                    \
    if (!_d) {                                                                        \
        asm volatile("{ .reg .pred P1; WL_%=: mbarrier.try_wait.parity.acquire.cta.shared::cta.b64 P1, [%0], %1, 0x989680; @P1 bra.uni WD_%=; bra.uni WL_%=; WD_%=: }" \
            :: "r"(_m), "r"(_p) : "memory");                                          \
    }                                                                                 \
} while (0)

#define TC_ALLOC(sa, n)   asm volatile("tcgen05.alloc.cta_group::1.sync.aligned.shared::cta.b32 [%0], %1;" :: "r"(sa), "r"(n) : "memory")
#define TC_DEALLOC(t, n)  asm volatile("tcgen05.dealloc.cta_group::1.sync.aligned.b32 %0, %1;" :: "r"(t), "r"(n))
#define TC_RELINQ()       asm volatile("tcgen05.relinquish_alloc_permit.cta_group::1.sync.aligned;")
#define TC_COMMIT(mb)     asm volatile("tcgen05.commit.cta_group::1.mbarrier::arrive::one.shared::cluster.b64 [%0];" :: "r"(mb) : "memory")
#define TC_FENCE_BEFORE() asm volatile("tcgen05.fence::before_thread_sync;" ::: "memory")
#define TC_FENCE_AFTER()  asm volatile("tcgen05.fence::after_thread_sync;" ::: "memory")
#define TC_WAIT_LD()      asm volatile("tcgen05.wait::ld.sync.aligned;" ::: "memory")
#define FENCE_ASYNC()     asm volatile("fence.proxy.async.shared::cta;" ::: "memory")

#define TC_LD_X32(r, ta) \
    asm volatile( \
        "tcgen05.ld.sync.aligned.32x32b.x32.b32 " \
        "{%0, %1, %2, %3, %4, %5, %6, %7, " \
        " %8, %9, %10, %11, %12, %13, %14, %15, " \
        " %16, %17, %18, %19, %20, %21, %22, %23, " \
        " %24, %25, %26, %27, %28, %29, %30, %31}, [%32];" \
        : "=r"((r)[0]),  "=r"((r)[1]),  "=r"((r)[2]),  "=r"((r)[3]), \
          "=r"((r)[4]),  "=r"((r)[5]),  "=r"((r)[6]),  "=r"((r)[7]), \
          "=r"((r)[8]),  "=r"((r)[9]),  "=r"((r)[10]), "=r"((r)[11]), \
          "=r"((r)[12]), "=r"((r)[13]), "=r"((r)[14]), "=r"((r)[15]), \
          "=r"((r)[16]), "=r"((r)[17]), "=r"((r)[18]), "=r"((r)[19]), \
          "=r"((r)[20]), "=r"((r)[21]), "=r"((r)[22]), "=r"((r)[23]), \
          "=r"((r)[24]), "=r"((r)[25]), "=r"((r)[26]), "=r"((r)[27]), \
          "=r"((r)[28]), "=r"((r)[29]), "=r"((r)[30]), "=r"((r)[31]) \
        : "r"(ta))

// SS-mode bf16 MMA, cta_group::1
__device__ __forceinline__ void mma_f16_ss(uint32_t d, uint64_t a, uint64_t b,
                                           uint32_t idesc, bool acc) {
    uint32_t en = acc ? 1u : 0u;
    asm volatile(
        "{\n\t.reg .pred p;\n\tsetp.ne.u32 p, %4, 0;\n\t"
        "tcgen05.mma.cta_group::1.kind::f16 [%0], %1, %2, %3, {%5,%5,%5,%5}, p;\n\t}"
        :: "r"(d), "l"(a), "l"(b), "r"(idesc), "r"(en), "r"(0u) : "memory");
}
#endif // HAS_TCGEN05

// SW128 K-major SMEM descriptor base (layout=SW128, version=1, SBO=64, LBO=1)
constexpr uint64_t DESC_BASE =
    (uint64_t(2) << 61) | (uint64_t(1) << 46) | (uint64_t(64) << 32) | (uint64_t(1) << 16);
__device__ __forceinline__ uint64_t make_desc(uint32_t smem_addr) {
    return DESC_BASE | ((uint64_t)(smem_addr >> 4) & 0x3FFF);
}

// idesc: f32 accum, bf16 A/B, K-major both, M=128, N=128
constexpr uint32_t MMA_IDESC =
    (1u << 4) | (1u << 7) | (1u << 10) | ((BN / 8) << 17) | ((BM / 16) << 24);

// Blocked-atom SW128 layout for a 128-row x 512-byte (256 bf16) tile.
__device__ __forceinline__ uint32_t tile_off(int row, int bytecol) {
    uint32_t off = (uint32_t)((((bytecol >> 7) << 4) + (row >> 3)) << 10)
                 + (uint32_t)((row & 7) << 7) + (uint32_t)(bytecol & 127);
    return off ^ ((off >> 3) & 0x70);
}
__device__ __forceinline__ uint32_t kstep_units(int k) {
    return (uint32_t)((k >> 2) * 1024 + (k & 3) * 2);
}

// ---------------- SMEM layout (offsets from the 1024-aligned base) ----------------
constexpr int SM_TMEMP = 0;
constexpr int SM_FULL0 = 8,  SM_FULL1 = 16;
constexpr int SM_MMA   = 24;                    // 4 x 8B : 24,32,40,48
constexpr int SM_EPI   = 56;                    // 4 x 8B : 56,64,72,80
constexpr int SM_ESQ   = 128;                   // 4 slots x 512B = 2048
constexpr int SM_X     = 4096;
constexpr int TILE_BYTES = BM * D_DIM * 2;      // 65536
constexpr int SM_E0    = SM_X + TILE_BYTES;
constexpr int SM_E1    = SM_E0 + TILE_BYTES;
constexpr int SMEM_TOTAL = SM_E1 + TILE_BYTES + 1024;   // alignment slack

constexpr int NTHREADS = 384;   // 8 epi warps + 1 MMA + 3 loaders

// ---------------- prep kernels ----------------
__global__ void prep_x(const float* __restrict__ X) {
    int i = blockIdx.x * blockDim.x + threadIdx.x;          // one uint4 (8 bf16) each
    const float4* s = reinterpret_cast<const float4*>(X) + (size_t)i * 2;
    float4 a = s[0], b = s[1];
    __nv_bfloat162 h0 = __floats2bfloat162_rn(a.x, a.y);
    __nv_bfloat162 h1 = __floats2bfloat162_rn(a.z, a.w);
    __nv_bfloat162 h2 = __floats2bfloat162_rn(b.x, b.y);
    __nv_bfloat162 h3 = __floats2bfloat162_rn(b.z, b.w);
    uint4 o;
    o.x = *reinterpret_cast<uint32_t*>(&h0);
    o.y = *reinterpret_cast<uint32_t*>(&h1);
    o.z = *reinterpret_cast<uint32_t*>(&h2);
    o.w = *reinterpret_cast<uint32_t*>(&h3);
    reinterpret_cast<uint4*>(g_Xb)[i] = o;
}

__global__ void prep_e(const float* __restrict__ E) {
    int gw = (blockIdx.x * blockDim.x + threadIdx.x) >> 5;
    int lane = threadIdx.x & 31;
    if (gw >= K_CB) return;
    const float4* e = reinterpret_cast<const float4*>(E + (size_t)gw * D_DIM);
    float4 v0 = e[lane], v1 = e[lane + 32];
    float s = v0.x * v0.x + v0.y * v0.y + v0.z * v0.z + v0.w * v0.w
            + v1.x * v1.x + v1.y * v1.y + v1.z * v1.z + v1.w * v1.w;
    __nv_bfloat162 h0 = __floats2bfloat162_rn(v0.x, v0.y);
    __nv_bfloat162 h1 = __floats2bfloat162_rn(v0.z, v0.w);
    __nv_bfloat162 h2 = __floats2bfloat162_rn(v1.x, v1.y);
    __nv_bfloat162 h3 = __floats2bfloat162_rn(v1.z, v1.w);
    uint2 o0 = { *reinterpret_cast<uint32_t*>(&h0), *reinterpret_cast<uint32_t*>(&h1) };
    uint2 o1 = { *reinterpret_cast<uint32_t*>(&h2), *reinterpret_cast<uint32_t*>(&h3) };
    *reinterpret_cast<uint2*>(g_Eb + (size_t)gw * D_DIM + lane * 4) = o0;
    *reinterpret_cast<uint2*>(g_Eb + (size_t)gw * D_DIM + 128 + lane * 4) = o1;
    #pragma unroll
    for (int o = 16; o > 0; o >>= 1) s += __shfl_xor_sync(0xFFFFFFFFu, s, o);
    if (lane == 0) g_esq[gw] = s;
}

// ---------------- stage 1 ----------------
__global__ void __launch_bounds__(NTHREADS, 1)
vq_stage1() {
    const int tid = threadIdx.x;
    const int rowBase = blockIdx.x * BM;
#if HAS_TCGEN05
    extern __shared__ char smem_raw[];
    const uint32_t sb0 = smem_u32(smem_raw);
    const uint32_t sb = (sb0 + 1023u) & ~1023u;        // 1024-aligned base
    char* smem = smem_raw + (sb - sb0);
    const int wid = tid >> 5;
    const int lane = tid & 31;

    if (wid == 8) {
        TC_ALLOC(sb + SM_TMEMP, 512);                  // 4 x 128-col D buffers
        TC_RELINQ();
    }
    if (tid == 0) {
        MBAR_INIT(sb + SM_FULL0, 96);  MBAR_INIT(sb + SM_FULL1, 96);
        #pragma unroll
        for (int i = 0; i < 4; i++) {
            MBAR_INIT(sb + SM_MMA + i * 8, 1);
            MBAR_INIT(sb + SM_EPI + i * 8, 256);
        }
    }
    __syncthreads();
    uint32_t tmem;
    asm volatile("ld.shared.b32 %0, [%1];" : "=r"(tmem) : "r"(sb + SM_TMEMP));

    // Stage X tile (128 x 256 bf16) once; all threads.
    for (int i = tid; i < 4096; i += NTHREADS) {
        int row = i >> 5, c16 = i & 31;
        uint4 v = *reinterpret_cast<const uint4*>(g_Xb + (size_t)(rowBase + row) * D_DIM + c16 * 8);
        *reinterpret_cast<uint4*>(smem + SM_X + tile_off(row, c16 * 16)) = v;
    }
    FENCE_ASYNC();
    __syncthreads();

    if (wid < 8) {
        // ---- epilogue: warp -> rows (wid&3)*32, col half (wid>>2) ----
        // NOTE: all register arrays below are accessed with compile-time
        // indices ONLY (fully unrolled loops) so they stay in registers.
        const int half  = wid >> 2;
        const int token = rowBase + (wid & 3) * 32 + lane;
        float best = FLT_MAX;
        int cnt = 0;
        int*   mylist = g_cand_idx + ((size_t)token * 2 + half) * CAP_H;
        float* myscr  = g_cand_scr + ((size_t)token * 2 + half) * CAP_H;

        for (int c = 0; c < NCHUNK; c++) {
            const int s4 = c & 3;
            MBAR_WAIT(sb + SM_MMA + s4 * 8, (c >> 2) & 1);
            TC_FENCE_AFTER();

            uint32_t r0[32], r1[32];
            const uint32_t tbase = tmem + (uint32_t)(s4 * 128 + half * 64);
            TC_LD_X32(r0, tbase);
            TC_LD_X32(r1, tbase + 32);

            const float4* esm = reinterpret_cast<const float4*>(
                smem + SM_ESQ + s4 * 512 + half * 256);
            TC_WAIT_LD();

            float sc0[32], sc1[32];
            #pragma unroll
            for (int g = 0; g < 8; g++) {
                float4 e = esm[g];
                sc0[g*4+0] = fmaf(-2.0f, __uint_as_float(r0[g*4+0]), e.x);
                sc0[g*4+1] = fmaf(-2.0f, __uint_as_float(r0[g*4+1]), e.y);
                sc0[g*4+2] = fmaf(-2.0f, __uint_as_float(r0[g*4+2]), e.z);
                sc0[g*4+3] = fmaf(-2.0f, __uint_as_float(r0[g*4+3]), e.w);
            }
            #pragma unroll
            for (int g = 0; g < 8; g++) {
                float4 e = esm[g + 8];
                sc1[g*4+0] = fmaf(-2.0f, __uint_as_float(r1[g*4+0]), e.x);
                sc1[g*4+1] = fmaf(-2.0f, __uint_as_float(r1[g*4+1]), e.y);
                sc1[g*4+2] = fmaf(-2.0f, __uint_as_float(r1[g*4+2]), e.z);
                sc1[g*4+3] = fmaf(-2.0f, __uint_as_float(r1[g*4+3]), e.w);
            }
            TC_FENCE_BEFORE();
            MBAR_ARRIVE(sb + SM_EPI + s4 * 8);    // TMEM buffer + esq slot free

            // log-depth min tree, constant indices only
            float t[32];
            #pragma unroll
            for (int j = 0; j < 32; j++) t[j] = fminf(sc0[j], sc1[j]);
            #pragma unroll
            for (int j = 0; j < 16; j++) t[j] = fminf(t[j], t[j + 16]);
            #pragma unroll
            for (int j = 0; j < 8; j++)  t[j] = fminf(t[j], t[j + 8]);
            #pragma unroll
            for (int j = 0; j < 4; j++)  t[j] = fminf(t[j], t[j + 4]);
            float m = fminf(fminf(t[0], t[1]), fminf(t[2], t[3]));

            if (m < best + MARGIN) {          // collect candidates (fully unrolled)
                const int colBase = c * BN + half * 64;
                #pragma unroll
                for (int j = 0; j < 32; j++) {
                    float v = sc0[j];
                    if (v < best + MARGIN) {
                        if (cnt < CAP_H) { mylist[cnt] = colBase + j; myscr[cnt] = v; }
                        cnt++;
                        if (v < best) best = v;
                    }
                }
                #pragma unroll
                for (int j = 0; j < 32; j++) {
                    float v = sc1[j];
                    if (v < best + MARGIN) {
                        if (cnt < CAP_H) { mylist[cnt] = colBase + 32 + j; myscr[cnt] = v; }
                        cnt++;
                        if (v < best) best = v;
                    }
                }
            }
        }
        g_cand_cnt[(size_t)token * 2 + half] = cnt;
    } else if (wid == 8) {
        // ---- MMA warp ----
        const uint64_t a_base = make_desc(sb + SM_X);
        for (int c = 0; c < NCHUNK; c++) {
            const int s2 = c & 1, s4 = c & 3;
            MBAR_WAIT(sb + (s2 ? SM_FULL1 : SM_FULL0), (c >> 1) & 1);
            if (c >= 4) MBAR_WAIT(sb + SM_EPI + s4 * 8, ((c - 4) >> 2) & 1);
            TC_FENCE_AFTER();
            if (elect_one()) {
                const uint64_t b_base = make_desc(sb + (s2 ? SM_E1 : SM_E0));
                #pragma unroll
                for (int k = 0; k < 16; k++) {
                    uint32_t u = kstep_units(k);
                    mma_f16_ss(tmem + (uint32_t)(s4 * 128), a_base + u, b_base + u,
                               MMA_IDESC, k > 0);
                }
                TC_COMMIT(sb + SM_MMA + s4 * 8);
            }
        }
    } else {
        // ---- loader warps (9..11, 96 threads) ----
        const int lt = tid - 288;
        for (int c = 0; c < NCHUNK; c++) {
            const int s2 = c & 1, s4 = c & 3;
            // E buffer s2 freed when MMA(c-2) finished reading SMEM
            if (c >= 2) MBAR_WAIT(sb + SM_MMA + ((c - 2) & 3) * 8, ((c - 2) >> 2) & 1);
            // esq slot s4 freed when EPI(c-4) consumed it
            if (c >= 4) MBAR_WAIT(sb + SM_EPI + s4 * 8, ((c - 4) >> 2) & 1);
            const int eoff = s2 ? SM_E1 : SM_E0;
            const size_t gbase = (size_t)(c * BN) * D_DIM;
            #pragma unroll 4
            for (int i = lt; i < 4096; i += 96) {
                int row = i >> 5, c16 = i & 31;
                uint4 v = *reinterpret_cast<const uint4*>(g_Eb + gbase + (size_t)row * D_DIM + c16 * 8);
                *reinterpret_cast<uint4*>(smem + eoff + tile_off(row, c16 * 16)) = v;
            }
            if (lt < 32) {   // esq chunk: 128 floats
                float4 v = *reinterpret_cast<const float4*>(g_esq + c * BN + lt * 4);
                *reinterpret_cast<float4*>(smem + SM_ESQ + s4 * 512 + lt * 16) = v;
            }
            FENCE_ASYNC();
            MBAR_ARRIVE(sb + (s2 ? SM_FULL1 : SM_FULL0));
        }
    }

    __syncthreads();
    if (wid == 8) TC_DEALLOC(tmem, 512);
#else
    // Stub pass: force stage-2 exact full scan for correctness.
    if (tid < BM) {
        g_cand_cnt[(size_t)(rowBase + tid) * 2 + 0] = CAP_H + 1;
        g_cand_cnt[(size_t)(rowBase + tid) * 2 + 1] = CAP_H + 1;
    }
#endif
}

// ---------------- stage 2: window-filtered exact rescore + gather ----------------
__global__ void vq_stage2(const float* __restrict__ X, const float* __restrict__ E,
                          float* __restrict__ out, int write_idx) {
    const int warp = (blockIdx.x * blockDim.x + threadIdx.x) >> 5;
    const int lane = threadIdx.x & 31;
    if (warp >= N_TOK) return;

    auto score = [&](int k, float4 x0, float4 x1) -> float {
        const float4* er = reinterpret_cast<const float4*>(E + (size_t)k * D_DIM) + lane * 2;
        float4 e0 = er[0], e1 = er[1];
        float d = x0.x * e0.x;
        d = fmaf(x0.y, e0.y, d); d = fmaf(x0.z, e0.z, d); d = fmaf(x0.w, e0.w, d);
        d = fmaf(x1.x, e1.x, d); d = fmaf(x1.y, e1.y, d);
        d = fmaf(x1.z, e1.z, d); d = fmaf(x1.w, e1.w, d);
        #pragma unroll
        for (int o = 16; o > 0; o >>= 1) d += __shfl_xor_sync(0xFFFFFFFFu, d, o);
        return fmaf(-2.0f, d, __ldg(&g_esq[k]));
    };

    const int cnt0 = g_cand_cnt[(size_t)warp * 2 + 0];
    const int cnt1 = g_cand_cnt[(size_t)warp * 2 + 1];
    int bi = 0;

    if (cnt0 <= CAP_H && cnt1 <= CAP_H) {
        const int*   l0 = g_cand_idx + (size_t)warp * 2 * CAP_H;
        const int*   l1 = l0 + CAP_H;
        const float* s0 = g_cand_scr + (size_t)warp * 2 * CAP_H;
        const float* s1 = s0 + CAP_H;

        // pass 1: min approx score
        float m = FLT_MAX;
        for (int t = 0; t < cnt0; t++) m = fminf(m, s0[t]);
        for (int t = 0; t < cnt1; t++) m = fminf(m, s1[t]);
        const float thr = m + RESCORE_MARGIN;

        // pass 2: collect window (true argmin is provably inside)
        int widx[16];
        int nw = 0;
        for (int t = 0; t < cnt0; t++)
            if (s0[t] < thr) { if (nw < 16) widx[nw] = l0[t]; nw++; }
        for (int t = 0; t < cnt1; t++)
            if (s1[t] < thr) { if (nw < 16) widx[nw] = l1[t]; nw++; }

        if (nw == 1) {
            bi = widx[0];                 // certain winner, no dot products
        } else {
            const float4* xr = reinterpret_cast<const float4*>(X + (size_t)warp * D_DIM) + lane * 2;
            const float4 x0 = xr[0], x1 = xr[1];
            float best = FLT_MAX;
            bi = 0x7FFFFFFF;
            if (nw <= 16) {
                for (int t = 0; t < nw; t++) {
                    int k = widx[t];
                    float scv = score(k, x0, x1);
                    if (scv < best || (scv == best && k < bi)) { best = scv; bi = k; }
                }
            } else {  // window overflow: rescore every candidate (rare)
                for (int t = 0; t < cnt0; t++) {
                    int k = l0[t];
                    float scv = score(k, x0, x1);
                    if (scv < best || (scv == best && k < bi)) { best = scv; bi = k; }
                }
                for (int t = 0; t < cnt1; t++) {
                    int k = l1[t];
                    float scv = score(k, x0, x1);
                    if (scv < best || (scv == best && k < bi)) { best = scv; bi = k; }
                }
            }
        }
    } else {
        // overflow / stub fallback: exact scan of all codes
        const float4* xr = reinterpret_cast<const float4*>(X + (size_t)warp * D_DIM) + lane * 2;
        const float4 x0 = xr[0], x1 = xr[1];
        float best = FLT_MAX;
        for (int k = 0; k < K_CB; k++) {
            float scv = score(k, x0, x1);
            if (scv < best) { best = scv; bi = k; }
        }
    }

    const float4* er = reinterpret_cast<const float4*>(E + (size_t)bi * D_DIM) + lane * 2;
    float4* outr = reinterpret_cast<float4*>(out + (size_t)warp * D_DIM) + lane * 2;
    outr[0] = er[0];
    outr[1] = er[1];
    if (write_idx && lane == 0)
        out[(size_t)N_TOK * D_DIM + warp] = (float)bi;
}

// ---------------- launcher ----------------
extern "C" void kernel_launch(void* const* d_in, const int* in_sizes, int n_in,
                              void* d_out, int out_size) {
    const float* X = (const float*)d_in[0];   // inputs_flatten [N, D]
    const float* E = (const float*)d_in[1];   // embed [K, D]
    float* out = (float*)d_out;

    cudaFuncSetAttribute(vq_stage1, cudaFuncAttributeMaxDynamicSharedMemorySize, SMEM_TOTAL);

    prep_x<<<(N_TOK * D_DIM / 8) / 256, 256>>>(X);
    prep_e<<<(K_CB * 32) / 256, 256>>>(E);
    vq_stage1<<<N_TOK / BM, NTHREADS, SMEM_TOTAL>>>();

    int write_idx = (out_size >= N_TOK * D_DIM + N_TOK) ? 1 : 0;
    vq_stage2<<<(N_TOK / 8), 256>>>(X, E, out, write_idx);
}